// round 1
// baseline (speedup 1.0000x reference)
#include <cuda_runtime.h>
#include <math.h>

// ---------------- static problem config ----------------
#define NNODES   102400          // 16 graphs * 6400 nodes
#define NEDGES   819200          // N * 8
#define NBATCH   16
#define GCELLS   72              // 8 * 9 voxel cells per graph
#define GXDIM    8
#define PSX      16.0f
#define PSY      12.0f
#define FC_IN    2304            // GCELLS * 32
#define NUM_OUT  2
#define NPG      6400

// ---------------- scratch (device globals; no allocation) ----------------
__device__ float    g_basis[(size_t)NEDGES * 8];   // basis sorted by dst
__device__ int      g_srcs [NEDGES];               // src sorted by dst
__device__ int      g_cnt  [NNODES];
__device__ int      g_rowp [NNODES + 1];
__device__ int      g_wcur [NNODES];
__device__ float    g_invc [NNODES];
__device__ float    g_bufA [(size_t)NNODES * 32];
__device__ float    g_bufB [(size_t)NNODES * 32];
__device__ float    g_bufC [(size_t)NNODES * 32];
__device__ unsigned g_pool [NBATCH * GCELLS * 32];
__device__ int      g_bsum [128];

// ---------------- helpers ----------------
__device__ __forceinline__ unsigned enc_f32(float f) {
    unsigned u = __float_as_uint(f);
    return (u & 0x80000000u) ? ~u : (u | 0x80000000u);
}
// encoded(-inf) = ~0xFF800000 = 0x007FFFFF

// ---------------- CSR build ----------------
__global__ void k_init() {
    int i = blockIdx.x * blockDim.x + threadIdx.x;
    if (i < NNODES) g_cnt[i] = 0;
    if (i < NBATCH * GCELLS * 32) g_pool[i] = 0x007FFFFFu;   // enc(-inf)
}

__global__ void k_count(const int* __restrict__ dst) {
    int e = blockIdx.x * blockDim.x + threadIdx.x;
    if (e < NEDGES) atomicAdd(&g_cnt[dst[e]], 1);
}

// 100 blocks, 256 threads, 4 elems/thread (102400 = 100*1024 exactly)
__global__ void k_scan1() {
    __shared__ int sm[256];
    int b = blockIdx.x, tid = threadIdx.x;
    int base = b * 1024 + tid * 4;
    int v0 = g_cnt[base + 0];
    int v1 = g_cnt[base + 1];
    int v2 = g_cnt[base + 2];
    int v3 = g_cnt[base + 3];
    int s = v0 + v1 + v2 + v3;
    sm[tid] = s;
    __syncthreads();
    for (int off = 1; off < 256; off <<= 1) {
        int t = (tid >= off) ? sm[tid - off] : 0;
        __syncthreads();
        sm[tid] += t;
        __syncthreads();
    }
    int excl = sm[tid] - s;   // block-local exclusive prefix
    g_rowp[base + 0] = excl;
    g_rowp[base + 1] = excl + v0;
    g_rowp[base + 2] = excl + v0 + v1;
    g_rowp[base + 3] = excl + v0 + v1 + v2;
    if (tid == 255) g_bsum[b] = sm[255];
}

__global__ void k_scan2() {
    // single thread over 100 block sums (trivial)
    int s = 0;
    for (int b = 0; b < 100; b++) { int t = g_bsum[b]; g_bsum[b] = s; s += t; }
}

__global__ void k_scan3() {
    int i = blockIdx.x * blockDim.x + threadIdx.x;
    if (i < NNODES) {
        int r = g_rowp[i] + g_bsum[i >> 10];
        g_rowp[i] = r;
        g_wcur[i] = r;
        int c = g_cnt[i];
        g_invc[i] = 1.0f / (float)(c > 0 ? c : 1);
    }
    if (i == 0) g_rowp[NNODES] = NEDGES;
}

__global__ void k_fill(const int* __restrict__ src, const int* __restrict__ dst,
                       const float* __restrict__ ea) {
    int e = blockIdx.x * blockDim.x + threadIdx.x;
    if (e >= NEDGES) return;
    int p = atomicAdd(&g_wcur[dst[e]], 1);
    g_srcs[p] = src[e];
    float u0 = fminf(fmaxf(ea[e * 3 + 0], 0.f), 1.f);
    float u1 = fminf(fmaxf(ea[e * 3 + 1], 0.f), 1.f);
    float u2 = fminf(fmaxf(ea[e * 3 + 2], 0.f), 1.f);
    float b0[2] = {1.f - u0, u0};
    float b1[2] = {1.f - u1, u1};
    float b2[2] = {1.f - u2, u2};
    float* bo = &g_basis[(size_t)p * 8];
#pragma unroll
    for (int k = 0; k < 8; k++)
        bo[k] = b0[k & 1] * b1[(k >> 1) & 1] * b2[(k >> 2) & 1];
}

// ---------------- fused spline conv ----------------
// agg[n, k*Cin+ci] = sum_{e: dst==n} basis[e,k] * hin[src_e, ci]
// out[n, co]       = ELU( inv_cnt[n] * sum_j agg[n,j] * W[j, co] ) (+ resid)
template <int Cin, int Cout>
__global__ void __launch_bounds__(256)
k_conv(const float* __restrict__ hin, float* __restrict__ hout,
       const float* __restrict__ resid, const float* __restrict__ W) {
    constexpr int KC = 8 * Cin;
    constexpr int WARPS = 8;
    constexpr int R = (KC + 31) / 32;
    __shared__ float sW[KC * Cout];
    __shared__ float sAgg[WARPS][KC];

    int tid = threadIdx.x, lane = tid & 31, w = tid >> 5;
    for (int i = tid; i < KC * Cout; i += 256) sW[i] = W[i];
    __syncthreads();

    int node = blockIdx.x * WARPS + w;
    if (node < NNODES) {
        int beg = g_rowp[node], end = g_rowp[node + 1];
        float acc[R];
#pragma unroll
        for (int r = 0; r < R; r++) acc[r] = 0.f;
        for (int e = beg; e < end; e++) {
            int s = g_srcs[e];
            float xv = hin[s * Cin + (lane % Cin)];
            const float* bp = &g_basis[(size_t)e * 8];
#pragma unroll
            for (int r = 0; r < R; r++) {
                int j = r * 32 + lane;
                if (j < KC) acc[r] = fmaf(bp[j / Cin], xv, acc[r]);
            }
        }
#pragma unroll
        for (int r = 0; r < R; r++) {
            int j = r * 32 + lane;
            if (j < KC) sAgg[w][j] = acc[r];
        }
    }
    __syncwarp();
    if (node < NNODES && lane < Cout) {
        float o = 0.f;
#pragma unroll 8
        for (int j = 0; j < KC; j++) o = fmaf(sAgg[w][j], sW[j * Cout + lane], o);
        o *= g_invc[node];
        o = (o > 0.f) ? o : expm1f(o);             // ELU
        if (resid) o += resid[node * Cout + lane];
        hout[node * Cout + lane] = o;
    }
}

// ---------------- voxel-grid max pool ----------------
__global__ void k_pool(const float* __restrict__ pos, const int* __restrict__ batch,
                       const float* __restrict__ h) {
    int i = blockIdx.x * blockDim.x + threadIdx.x;
    if (i >= NNODES * 32) return;
    int n = i >> 5, c = i & 31;
    float px = pos[n * 3 + 0], py = pos[n * 3 + 1];
    int cx = (int)floorf(px / PSX);
    int cy = (int)floorf(py / PSY);
    int cl = batch[n] * GCELLS + cy * GXDIM + cx;
    atomicMax(&g_pool[cl * 32 + c], enc_f32(h[i]));
}

// ---------------- FC head ----------------
__global__ void k_fc(const float* __restrict__ fcw, float* __restrict__ out) {
    __shared__ float s0[256], s1[256];
    int b = blockIdx.x, tid = threadIdx.x;
    float a0 = 0.f, a1 = 0.f;
    for (int j = tid; j < FC_IN; j += 256) {
        unsigned u = g_pool[b * FC_IN + j];
        float v = (u & 0x80000000u) ? __uint_as_float(u & 0x7fffffffu)
                                    : __uint_as_float(~u);
        if (!isfinite(v)) v = 0.f;                 // empty cell -> 0
        a0 = fmaf(v, fcw[j * 2 + 0], a0);
        a1 = fmaf(v, fcw[j * 2 + 1], a1);
    }
    s0[tid] = a0; s1[tid] = a1;
    __syncthreads();
    for (int o = 128; o > 0; o >>= 1) {
        if (tid < o) { s0[tid] += s0[tid + o]; s1[tid] += s1[tid + o]; }
        __syncthreads();
    }
    if (tid == 0) { out[b * 2 + 0] = s0[0]; out[b * 2 + 1] = s1[0]; }
}

// ---------------- launch ----------------
extern "C" void kernel_launch(void* const* d_in, const int* in_sizes, int n_in,
                              void* d_out, int out_size) {
    const float* x     = (const float*)d_in[0];
    const float* pos   = (const float*)d_in[1];
    const float* ea    = (const float*)d_in[2];
    const int*   ei    = (const int*)  d_in[3];
    const int*   batch = (const int*)  d_in[4];
    const float* fcw   = (const float*)d_in[5];
    const float* w1 = (const float*)d_in[6];
    const float* w2 = (const float*)d_in[7];
    const float* w3 = (const float*)d_in[8];
    const float* w4 = (const float*)d_in[9];
    const float* w5 = (const float*)d_in[10];
    const float* w6 = (const float*)d_in[11];
    const float* w7 = (const float*)d_in[12];
    const int* src = ei;
    const int* dst = ei + NEDGES;

    void *pA, *pB, *pC;
    cudaGetSymbolAddress(&pA, g_bufA);
    cudaGetSymbolAddress(&pB, g_bufB);
    cudaGetSymbolAddress(&pC, g_bufC);
    float* A = (float*)pA; float* Bb = (float*)pB; float* C = (float*)pC;

    k_init <<<(NNODES + 255) / 256, 256>>>();
    k_count<<<NEDGES / 256, 256>>>(dst);
    k_scan1<<<100, 256>>>();
    k_scan2<<<1, 1>>>();
    k_scan3<<<NNODES / 256, 256>>>();
    k_fill <<<NEDGES / 256, 256>>>(src, dst, ea);

    const int CB = (NNODES + 7) / 8;   // 12800 blocks, 8 warps (nodes) each
    k_conv<1,  8 ><<<CB, 256>>>(x,  A,  nullptr, w1);
    k_conv<8,  16><<<CB, 256>>>(A,  Bb, nullptr, w2);
    k_conv<16, 16><<<CB, 256>>>(Bb, A,  nullptr, w3);
    k_conv<16, 16><<<CB, 256>>>(A,  C,  Bb,      w4);   // + h2 residual
    k_conv<16, 32><<<CB, 256>>>(C,  A,  nullptr, w5);
    k_conv<32, 32><<<CB, 256>>>(A,  Bb, nullptr, w6);
    k_conv<32, 32><<<CB, 256>>>(Bb, C,  A,       w7);   // + h5 residual

    k_pool<<<(NNODES * 32) / 256, 256>>>(pos, batch, C);
    k_fc  <<<NBATCH, 256>>>(fcw, (float*)d_out);
}

// round 2
// speedup vs baseline: 1.1147x; 1.1147x over previous
#include <cuda_runtime.h>
#include <math.h>

// ---------------- static problem config ----------------
#define NNODES   102400
#define NEDGES   819200
#define NBATCH   16
#define GCELLS   72
#define GXDIM    8
#define PSX      16.0f
#define PSY      12.0f
#define FC_IN    2304
#define NTILES   (NNODES / 8)     // 12800

// ---------------- scratch (device globals; no allocation) ----------------
__device__ float    g_basis[(size_t)NEDGES * 8];
__device__ int      g_srcs [NEDGES];
__device__ int      g_cnt  [NNODES];
__device__ int      g_rowp [NNODES + 1];
__device__ int      g_wcur [NNODES];
__device__ float    g_invc [NNODES];
__device__ float    g_bufA [(size_t)NNODES * 32];
__device__ float    g_bufB [(size_t)NNODES * 32];
__device__ float    g_bufC [(size_t)NNODES * 32];
__device__ unsigned g_pool [NBATCH * GCELLS * 32];
__device__ int      g_bsum [128];

// ---------------- packed fp32x2 helpers (sm_103a FFMA2) ----------------
typedef unsigned long long u64;
__device__ __forceinline__ u64 pack2(float lo, float hi) {
    u64 r;
    asm("mov.b64 %0, {%1,%2};" : "=l"(r)
        : "r"(__float_as_uint(lo)), "r"(__float_as_uint(hi)));
    return r;
}
__device__ __forceinline__ float2 unpack2(u64 v) {
    unsigned lo, hi;
    asm("mov.b64 {%0,%1}, %2;" : "=r"(lo), "=r"(hi) : "l"(v));
    return make_float2(__uint_as_float(lo), __uint_as_float(hi));
}
__device__ __forceinline__ u64 fma2(u64 a, u64 b, u64 c) {
    u64 d;
    asm("fma.rn.f32x2 %0, %1, %2, %3;" : "=l"(d) : "l"(a), "l"(b), "l"(c));
    return d;
}

__device__ __forceinline__ unsigned enc_f32(float f) {
    unsigned u = __float_as_uint(f);
    return (u & 0x80000000u) ? ~u : (u | 0x80000000u);
}

// ---------------- CSR build ----------------
__global__ void k_init() {
    int i = blockIdx.x * blockDim.x + threadIdx.x;
    if (i < NNODES) g_cnt[i] = 0;
    if (i < NBATCH * GCELLS * 32) g_pool[i] = 0x007FFFFFu;   // enc(-inf)
}

__global__ void k_count(const int* __restrict__ dst) {
    int e = blockIdx.x * blockDim.x + threadIdx.x;
    if (e < NEDGES) atomicAdd(&g_cnt[dst[e]], 1);
}

__global__ void k_scan1() {
    __shared__ int sm[256];
    int b = blockIdx.x, tid = threadIdx.x;
    int base = b * 1024 + tid * 4;
    int v0 = g_cnt[base + 0], v1 = g_cnt[base + 1];
    int v2 = g_cnt[base + 2], v3 = g_cnt[base + 3];
    int s = v0 + v1 + v2 + v3;
    sm[tid] = s;
    __syncthreads();
    for (int off = 1; off < 256; off <<= 1) {
        int t = (tid >= off) ? sm[tid - off] : 0;
        __syncthreads();
        sm[tid] += t;
        __syncthreads();
    }
    int excl = sm[tid] - s;
    g_rowp[base + 0] = excl;
    g_rowp[base + 1] = excl + v0;
    g_rowp[base + 2] = excl + v0 + v1;
    g_rowp[base + 3] = excl + v0 + v1 + v2;
    if (tid == 255) g_bsum[b] = sm[255];
}

__global__ void k_scan2() {   // 1 block, 128 threads
    __shared__ int sm[128];
    int t = threadIdx.x;
    int v = (t < 100) ? g_bsum[t] : 0;
    sm[t] = v;
    __syncthreads();
    for (int off = 1; off < 128; off <<= 1) {
        int a = (t >= off) ? sm[t - off] : 0;
        __syncthreads();
        sm[t] += a;
        __syncthreads();
    }
    if (t < 100) g_bsum[t] = sm[t] - v;   // exclusive
}

__global__ void k_scan3() {
    int i = blockIdx.x * blockDim.x + threadIdx.x;
    if (i < NNODES) {
        int r = g_rowp[i] + g_bsum[i >> 10];
        g_rowp[i] = r;
        g_wcur[i] = r;
        int c = g_cnt[i];
        g_invc[i] = 1.0f / (float)(c > 0 ? c : 1);
    }
    if (i == 0) g_rowp[NNODES] = NEDGES;
}

__global__ void k_fill(const int* __restrict__ src, const int* __restrict__ dst,
                       const float* __restrict__ ea) {
    int e = blockIdx.x * blockDim.x + threadIdx.x;
    if (e >= NEDGES) return;
    int p = atomicAdd(&g_wcur[dst[e]], 1);
    g_srcs[p] = src[e];
    float u0 = fminf(fmaxf(ea[e * 3 + 0], 0.f), 1.f);
    float u1 = fminf(fmaxf(ea[e * 3 + 1], 0.f), 1.f);
    float u2 = fminf(fmaxf(ea[e * 3 + 2], 0.f), 1.f);
    float m0 = 1.f - u0, m1 = 1.f - u1, m2 = 1.f - u2;
    float4 lo = make_float4(m0 * m1 * m2, u0 * m1 * m2, m0 * u1 * m2, u0 * u1 * m2);
    float4 hi = make_float4(m0 * m1 * u2, u0 * m1 * u2, m0 * u1 * u2, u0 * u1 * u2);
    float4* bo = (float4*)(g_basis + (size_t)p * 8);
    bo[0] = lo; bo[1] = hi;
}

// ---------------- conv1 (Cin=1 -> Cout=8), lane-per-edge ----------------
__global__ void __launch_bounds__(256)
k_conv1(const float* __restrict__ x, float* __restrict__ hout,
        const float* __restrict__ W) {
    int tid = threadIdx.x, lane = tid & 31, w = tid >> 5;
    float wreg[8];
#pragma unroll
    for (int k = 0; k < 8; k++) wreg[k] = __ldg(&W[k * 8 + (lane & 7)]);
    for (int node = blockIdx.x * 8 + w; node < NNODES; node += gridDim.x * 8) {
        int beg = g_rowp[node], end = g_rowp[node + 1];
        float a[8] = {0, 0, 0, 0, 0, 0, 0, 0};
        for (int e = beg + lane; e < end; e += 32) {
            float xv = __ldg(&x[g_srcs[e]]);
            const float4* bp = (const float4*)(g_basis + (size_t)e * 8);
            float4 b0 = __ldg(bp), b1 = __ldg(bp + 1);
            a[0] = fmaf(b0.x, xv, a[0]); a[1] = fmaf(b0.y, xv, a[1]);
            a[2] = fmaf(b0.z, xv, a[2]); a[3] = fmaf(b0.w, xv, a[3]);
            a[4] = fmaf(b1.x, xv, a[4]); a[5] = fmaf(b1.y, xv, a[5]);
            a[6] = fmaf(b1.z, xv, a[6]); a[7] = fmaf(b1.w, xv, a[7]);
        }
#pragma unroll
        for (int k = 0; k < 8; k++)
#pragma unroll
            for (int off = 16; off; off >>= 1)
                a[k] += __shfl_xor_sync(0xffffffffu, a[k], off);
        if (lane < 8) {
            float o = 0.f;
#pragma unroll
            for (int k = 0; k < 8; k++) o = fmaf(a[k], wreg[k], o);
            o *= g_invc[node];
            o = (o > 0.f) ? o : expm1f(o);
            hout[(size_t)node * 8 + lane] = o;
        }
    }
}

// ---------------- fused spline conv (Cin in {8,16,32}) ----------------
// Tile = 8 nodes. Warp w aggregates node w of the tile into transposed smem
// sAggT[j][node]. GEMM: warp w owns j-chunk [w*CJ, (w+1)*CJ), W slice cached
// in registers, accumulates node-pairs with packed f32x2 FMA; partials reduced
// across warps through sPart. Epilogue: mean, ELU, residual, optional pool.
template <int Cin, int Cout, bool POOL>
__global__ void __launch_bounds__(256)
k_conv(const float* __restrict__ hin, float* __restrict__ hout,
       const float* __restrict__ resid, const float* __restrict__ W,
       const float* __restrict__ pos, const int* __restrict__ batch) {
    constexpr int KC = 8 * Cin;
    constexpr int R  = KC / 32;          // 2,4,8
    constexpr int RP = R / 2;            // 1,2,4
    constexpr int CJ = KC / 8;           // 8,16,32
    constexpr int NPAIR = (Cout == 32) ? 4 : 2;
    __shared__ __align__(16) float sAggT[KC][10];       // [j][node], pad 10
    __shared__ __align__(16) float sPart[8][8][Cout];

    int tid = threadIdx.x, lane = tid & 31, w = tid >> 5;
    int ci = lane & (Cin - 1);
    int coLane = lane & (Cout - 1);
    int hi16 = lane >> 4;
    int qq = (lane >> 3) & 3;

    float Wreg[CJ];
#pragma unroll
    for (int i = 0; i < CJ; i++) Wreg[i] = __ldg(&W[(w * CJ + i) * Cout + coLane]);

    for (int tile = blockIdx.x; tile < NTILES; tile += gridDim.x) {
        int node = tile * 8 + w;
        int beg = g_rowp[node], end = g_rowp[node + 1];
        int deg = end - beg;

        // ---- aggregation ----
        u64 acc2[RP];
#pragma unroll
        for (int q = 0; q < RP; q++) acc2[q] = 0ull;
        int degc = deg < 32 ? deg : 32;
        int s_l = (lane < degc) ? g_srcs[beg + lane] : 0;

        for (int e0 = 0; e0 < degc; e0 += 4) {
            float xv[4]; float4 ba[4], bb[4];
#pragma unroll
            for (int u = 0; u < 4; u++) {
                int e = e0 + u;
                bool p = e < degc;
                int s = __shfl_sync(0xffffffffu, s_l, e & 31);
                xv[u] = p ? __ldg(&hin[(size_t)s * Cin + ci]) : 0.f;
                const float4* bp = (const float4*)(g_basis + (size_t)(beg + (p ? e : 0)) * 8);
                ba[u] = __ldg(bp); bb[u] = __ldg(bp + 1);
            }
#pragma unroll
            for (int u = 0; u < 4; u++) {
                u64 x2 = pack2(xv[u], xv[u]);
                float b[8] = {ba[u].x, ba[u].y, ba[u].z, ba[u].w,
                              bb[u].x, bb[u].y, bb[u].z, bb[u].w};
#pragma unroll
                for (int q = 0; q < RP; q++) {
                    float blo, bhi;
                    if (Cin == 32)      { blo = b[2 * q];     bhi = b[2 * q + 1]; }
                    else if (Cin == 16) { blo = hi16 ? b[4 * q + 1] : b[4 * q];
                                          bhi = hi16 ? b[4 * q + 3] : b[4 * q + 2]; }
                    else {              // Cin == 8
                        float t01 = (qq & 1) ? b[1] : b[0];
                        float t23 = (qq & 1) ? b[3] : b[2];
                        blo = (qq & 2) ? t23 : t01;
                        float u01 = (qq & 1) ? b[5] : b[4];
                        float u23 = (qq & 1) ? b[7] : b[6];
                        bhi = (qq & 2) ? u23 : u01;
                    }
                    acc2[q] = fma2(pack2(blo, bhi), x2, acc2[q]);
                }
            }
        }
        for (int e = 32; e < deg; e++) {          // rare high-degree tail
            int s = g_srcs[beg + e];
            float xv = __ldg(&hin[(size_t)s * Cin + ci]);
            const float4* bp = (const float4*)(g_basis + (size_t)(beg + e) * 8);
            float4 t0 = __ldg(bp), t1 = __ldg(bp + 1);
            u64 x2 = pack2(xv, xv);
            float b[8] = {t0.x, t0.y, t0.z, t0.w, t1.x, t1.y, t1.z, t1.w};
#pragma unroll
            for (int q = 0; q < RP; q++) {
                float blo, bhi;
                if (Cin == 32)      { blo = b[2 * q];     bhi = b[2 * q + 1]; }
                else if (Cin == 16) { blo = hi16 ? b[4 * q + 1] : b[4 * q];
                                      bhi = hi16 ? b[4 * q + 3] : b[4 * q + 2]; }
                else {
                    float t01 = (qq & 1) ? b[1] : b[0];
                    float t23 = (qq & 1) ? b[3] : b[2];
                    blo = (qq & 2) ? t23 : t01;
                    float u01 = (qq & 1) ? b[5] : b[4];
                    float u23 = (qq & 1) ? b[7] : b[6];
                    bhi = (qq & 2) ? u23 : u01;
                }
                acc2[q] = fma2(pack2(blo, bhi), x2, acc2[q]);
            }
        }
#pragma unroll
        for (int q = 0; q < RP; q++) {
            float2 v = unpack2(acc2[q]);
            sAggT[(2 * q) * 32 + lane][w]     = v.x;
            sAggT[(2 * q + 1) * 32 + lane][w] = v.y;
        }
        __syncthreads();

        // ---- GEMM: warp w handles its CJ-row slice for all 8 nodes ----
        u64 gac[NPAIR];
#pragma unroll
        for (int p = 0; p < NPAIR; p++) gac[p] = 0ull;
#pragma unroll
        for (int i = 0; i < CJ; i++) {
            int j = w * CJ + i;
            u64 w2 = pack2(Wreg[i], Wreg[i]);
#pragma unroll
            for (int p = 0; p < NPAIR; p++) {
                int pp = (Cout == 32) ? p : (p * 2 + hi16);
                u64 a2 = *(const u64*)&sAggT[j][2 * pp];
                gac[p] = fma2(a2, w2, gac[p]);
            }
        }
#pragma unroll
        for (int p = 0; p < NPAIR; p++) {
            int pp = (Cout == 32) ? p : (p * 2 + hi16);
            float2 v = unpack2(gac[p]);
            sPart[w][2 * pp][coLane]     = v.x;
            sPart[w][2 * pp + 1][coLane] = v.y;
        }
        __syncthreads();

        // ---- reduce partials + epilogue ----
        if (tid < 8 * Cout) {
            int n  = tid / Cout;
            int co = tid % Cout;
            float s = 0.f;
#pragma unroll
            for (int ww = 0; ww < 8; ww++) s += sPart[ww][n][co];
            int node2 = tile * 8 + n;
            s *= g_invc[node2];
            s = (s > 0.f) ? s : expm1f(s);
            if (resid) s += resid[(size_t)node2 * Cout + co];
            if (POOL) {
                float px = pos[node2 * 3 + 0], py = pos[node2 * 3 + 1];
                int cx = (int)floorf(px / PSX);
                int cy = (int)floorf(py / PSY);
                int cl = batch[node2] * GCELLS + cy * GXDIM + cx;
                atomicMax(&g_pool[cl * 32 + co], enc_f32(s));
            } else {
                hout[(size_t)node2 * Cout + co] = s;
            }
        }
        __syncthreads();
    }
}

// ---------------- FC head ----------------
__global__ void k_fc(const float* __restrict__ fcw, float* __restrict__ out) {
    __shared__ float s0[256], s1[256];
    int b = blockIdx.x, tid = threadIdx.x;
    float a0 = 0.f, a1 = 0.f;
    for (int j = tid; j < FC_IN; j += 256) {
        unsigned u = g_pool[b * FC_IN + j];
        float v = (u & 0x80000000u) ? __uint_as_float(u & 0x7fffffffu)
                                    : __uint_as_float(~u);
        if (!isfinite(v)) v = 0.f;
        a0 = fmaf(v, fcw[j * 2 + 0], a0);
        a1 = fmaf(v, fcw[j * 2 + 1], a1);
    }
    s0[tid] = a0; s1[tid] = a1;
    __syncthreads();
    for (int o = 128; o > 0; o >>= 1) {
        if (tid < o) { s0[tid] += s0[tid + o]; s1[tid] += s1[tid + o]; }
        __syncthreads();
    }
    if (tid == 0) { out[b * 2 + 0] = s0[0]; out[b * 2 + 1] = s1[0]; }
}

// ---------------- launch ----------------
extern "C" void kernel_launch(void* const* d_in, const int* in_sizes, int n_in,
                              void* d_out, int out_size) {
    const float* x     = (const float*)d_in[0];
    const float* pos   = (const float*)d_in[1];
    const float* ea    = (const float*)d_in[2];
    const int*   ei    = (const int*)  d_in[3];
    const int*   batch = (const int*)  d_in[4];
    const float* fcw   = (const float*)d_in[5];
    const float* w1 = (const float*)d_in[6];
    const float* w2 = (const float*)d_in[7];
    const float* w3 = (const float*)d_in[8];
    const float* w4 = (const float*)d_in[9];
    const float* w5 = (const float*)d_in[10];
    const float* w6 = (const float*)d_in[11];
    const float* w7 = (const float*)d_in[12];
    const int* src = ei;
    const int* dst = ei + NEDGES;

    void *pA, *pB, *pC;
    cudaGetSymbolAddress(&pA, g_bufA);
    cudaGetSymbolAddress(&pB, g_bufB);
    cudaGetSymbolAddress(&pC, g_bufC);
    float* A = (float*)pA; float* Bb = (float*)pB; float* C = (float*)pC;

    k_init <<<(NNODES + 255) / 256, 256>>>();
    k_count<<<NEDGES / 256, 256>>>(dst);
    k_scan1<<<100, 256>>>();
    k_scan2<<<1, 128>>>();
    k_scan3<<<NNODES / 256, 256>>>();
    k_fill <<<NEDGES / 256, 256>>>(src, dst, ea);

    const int CG = 1280;   // grid-stride over 12800 tiles
    k_conv1<<<1600, 256>>>(x, A, w1);
    k_conv<8,  16, false><<<CG, 256>>>(A,  Bb, nullptr, w2, pos, batch);
    k_conv<16, 16, false><<<CG, 256>>>(Bb, A,  nullptr, w3, pos, batch);
    k_conv<16, 16, false><<<CG, 256>>>(A,  C,  Bb,      w4, pos, batch);
    k_conv<16, 32, false><<<CG, 256>>>(C,  A,  nullptr, w5, pos, batch);
    k_conv<32, 32, false><<<CG, 256>>>(A,  Bb, nullptr, w6, pos, batch);
    k_conv<32, 32, true ><<<CG, 256>>>(Bb, C,  A,       w7, pos, batch);  // fused pool

    k_fc<<<NBATCH, 256>>>(fcw, (float*)d_out);
}

// round 3
// speedup vs baseline: 1.3658x; 1.2253x over previous
#include <cuda_runtime.h>
#include <math.h>

// ---------------- static problem config ----------------
#define NNODES   102400
#define NEDGES   819200
#define NBATCH   16
#define GCELLS   72
#define GXDIM    8
#define PSX      16.0f
#define PSY      12.0f
#define FC_IN    2304
#define NTILES   12800           // NNODES / 8
#define NBLK     592             // 148 SMs * 4 blocks (full co-residency)
#define NTHR     256

// ---------------- scratch (device globals; no allocation) ----------------
__device__ float    g_basis[(size_t)NEDGES * 8];
__device__ int      g_srcs [NEDGES];
__device__ int      g_cnt  [NNODES];
__device__ int      g_rowp [NNODES + 1];
__device__ int      g_wcur [NNODES];
__device__ float    g_invc [NNODES];
__device__ float    g_bufA [(size_t)NNODES * 32];
__device__ float    g_bufB [(size_t)NNODES * 32];
__device__ float    g_bufC [(size_t)NNODES * 32];
__device__ unsigned g_pool [NBATCH * GCELLS * 32];
__device__ int      g_bsum [128];
__device__ unsigned g_bar_gen;   // persistent generation counter
__device__ unsigned g_bar_cnt;

// ---------------- packed fp32x2 helpers (sm_103a FFMA2) ----------------
typedef unsigned long long u64;
__device__ __forceinline__ u64 pack2(float lo, float hi) {
    u64 r;
    asm("mov.b64 %0, {%1,%2};" : "=l"(r)
        : "r"(__float_as_uint(lo)), "r"(__float_as_uint(hi)));
    return r;
}
__device__ __forceinline__ float2 unpack2(u64 v) {
    unsigned lo, hi;
    asm("mov.b64 {%0,%1}, %2;" : "=r"(lo), "=r"(hi) : "l"(v));
    return make_float2(__uint_as_float(lo), __uint_as_float(hi));
}
__device__ __forceinline__ u64 fma2(u64 a, u64 b, u64 c) {
    u64 d;
    asm("fma.rn.f32x2 %0, %1, %2, %3;" : "=l"(d) : "l"(a), "l"(b), "l"(c));
    return d;
}
__device__ __forceinline__ unsigned enc_f32(float f) {
    unsigned u = __float_as_uint(f);
    return (u & 0x80000000u) ? ~u : (u | 0x80000000u);
}
__device__ __forceinline__ float fast_elu(float o) {
    return (o > 0.f) ? o : (__expf(o) - 1.0f);
}

// ---------------- software grid barrier ----------------
// All threads fence (gpu scope -> CCTL.IVALL: releases stores + invalidates
// this SM's L1 so cross-phase buffer reuse is coherent). Thread 0 arrives;
// last block bumps the generation. Requires full grid co-residency
// (guaranteed by __launch_bounds__(256, 4) and NBLK = 148*4).
__device__ __forceinline__ void grid_barrier(unsigned target) {
    __threadfence();
    __syncthreads();
    if (threadIdx.x == 0) {
        unsigned my = atomicAdd(&g_bar_cnt, 1u);
        if (my == NBLK - 1u) {
            g_bar_cnt = 0u;
            __threadfence();
            atomicExch(&g_bar_gen, target);
        } else {
            while (*(volatile unsigned*)&g_bar_gen < target) { __nanosleep(64); }
        }
    }
    __syncthreads();
}

// ---------------- conv1 phase (Cin=1 -> Cout=8), lane-per-edge ----------------
__device__ void conv1_phase(const float* __restrict__ x, float* __restrict__ hout,
                            const float* __restrict__ W) {
    int tid = threadIdx.x, lane = tid & 31, w = tid >> 5;
    float wreg[8];
#pragma unroll
    for (int k = 0; k < 8; k++) wreg[k] = __ldg(&W[k * 8 + (lane & 7)]);
    for (int node = blockIdx.x * 8 + w; node < NNODES; node += NBLK * 8) {
        int beg = g_rowp[node], end = g_rowp[node + 1];
        float a[8] = {0, 0, 0, 0, 0, 0, 0, 0};
        for (int e = beg + lane; e < end; e += 32) {
            float xv = __ldg(&x[g_srcs[e]]);
            const float4* bp = (const float4*)(g_basis + (size_t)e * 8);
            float4 b0 = __ldg(bp), b1 = __ldg(bp + 1);
            a[0] = fmaf(b0.x, xv, a[0]); a[1] = fmaf(b0.y, xv, a[1]);
            a[2] = fmaf(b0.z, xv, a[2]); a[3] = fmaf(b0.w, xv, a[3]);
            a[4] = fmaf(b1.x, xv, a[4]); a[5] = fmaf(b1.y, xv, a[5]);
            a[6] = fmaf(b1.z, xv, a[6]); a[7] = fmaf(b1.w, xv, a[7]);
        }
#pragma unroll
        for (int k = 0; k < 8; k++)
#pragma unroll
            for (int off = 16; off; off >>= 1)
                a[k] += __shfl_xor_sync(0xffffffffu, a[k], off);
        if (lane < 8) {
            float o = 0.f;
#pragma unroll
            for (int k = 0; k < 8; k++) o = fmaf(a[k], wreg[k], o);
            o *= g_invc[node];
            hout[(size_t)node * 8 + lane] = fast_elu(o);
        }
    }
}

// ---------------- fused spline conv phase (Cin in {8,16,32}) ----------------
template <int Cin, int Cout, bool POOL>
__device__ void conv_phase(const float* __restrict__ hin, float* __restrict__ hout,
                           const float* __restrict__ resid, const float* __restrict__ W,
                           const float* __restrict__ pos, const int* __restrict__ batch,
                           float (&sAggT)[256][10], float* sPart) {
    constexpr int KC = 8 * Cin;
    constexpr int RP = KC / 64;          // u64 accumulators per lane: 1,2,4
    constexpr int CJ = KC / 8;           // j-rows per warp: 8,16,32
    constexpr int NPAIR = (Cout == 32) ? 4 : 2;

    int tid = threadIdx.x, lane = tid & 31, w = tid >> 5;
    int ci = lane & (Cin - 1);
    int coLane = lane & (Cout - 1);
    int hi16 = lane >> 4;
    int qq = (lane >> 3) & 3;

    for (int tile = blockIdx.x; tile < NTILES; tile += NBLK) {
        int node = tile * 8 + w;
        int beg = g_rowp[node], end = g_rowp[node + 1];
        int deg = end - beg;

        // ---- aggregation: acc2 holds (k,ci) lanes packed as f32x2 ----
        u64 acc2[RP];
#pragma unroll
        for (int q = 0; q < RP; q++) acc2[q] = 0ull;
        int degc = deg < 32 ? deg : 32;
        int s_l = (lane < degc) ? g_srcs[beg + lane] : 0;

        for (int e0 = 0; e0 < degc; e0 += 4) {
            float xv[4]; float4 ba[4], bb[4];
#pragma unroll
            for (int u = 0; u < 4; u++) {
                int e = e0 + u;
                bool p = e < degc;
                int s = __shfl_sync(0xffffffffu, s_l, e & 31);
                xv[u] = p ? __ldg(&hin[(size_t)s * Cin + ci]) : 0.f;
                const float4* bp = (const float4*)(g_basis + (size_t)(beg + (p ? e : 0)) * 8);
                ba[u] = __ldg(bp); bb[u] = __ldg(bp + 1);
            }
#pragma unroll
            for (int u = 0; u < 4; u++) {
                u64 x2 = pack2(xv[u], xv[u]);
                float b[8] = {ba[u].x, ba[u].y, ba[u].z, ba[u].w,
                              bb[u].x, bb[u].y, bb[u].z, bb[u].w};
#pragma unroll
                for (int q = 0; q < RP; q++) {
                    float blo, bhi;
                    if (Cin == 32)      { blo = b[2 * q];     bhi = b[2 * q + 1]; }
                    else if (Cin == 16) { blo = hi16 ? b[4 * q + 1] : b[4 * q];
                                          bhi = hi16 ? b[4 * q + 3] : b[4 * q + 2]; }
                    else {
                        float t01 = (qq & 1) ? b[1] : b[0];
                        float t23 = (qq & 1) ? b[3] : b[2];
                        blo = (qq & 2) ? t23 : t01;
                        float u01 = (qq & 1) ? b[5] : b[4];
                        float u23 = (qq & 1) ? b[7] : b[6];
                        bhi = (qq & 2) ? u23 : u01;
                    }
                    acc2[q] = fma2(pack2(blo, bhi), x2, acc2[q]);
                }
            }
        }
        for (int e = 32; e < deg; e++) {          // rare high-degree tail
            int s = g_srcs[beg + e];
            float xv = __ldg(&hin[(size_t)s * Cin + ci]);
            const float4* bp = (const float4*)(g_basis + (size_t)(beg + e) * 8);
            float4 t0 = __ldg(bp), t1 = __ldg(bp + 1);
            u64 x2 = pack2(xv, xv);
            float b[8] = {t0.x, t0.y, t0.z, t0.w, t1.x, t1.y, t1.z, t1.w};
#pragma unroll
            for (int q = 0; q < RP; q++) {
                float blo, bhi;
                if (Cin == 32)      { blo = b[2 * q];     bhi = b[2 * q + 1]; }
                else if (Cin == 16) { blo = hi16 ? b[4 * q + 1] : b[4 * q];
                                      bhi = hi16 ? b[4 * q + 3] : b[4 * q + 2]; }
                else {
                    float t01 = (qq & 1) ? b[1] : b[0];
                    float t23 = (qq & 1) ? b[3] : b[2];
                    blo = (qq & 2) ? t23 : t01;
                    float u01 = (qq & 1) ? b[5] : b[4];
                    float u23 = (qq & 1) ? b[7] : b[6];
                    bhi = (qq & 2) ? u23 : u01;
                }
                acc2[q] = fma2(pack2(blo, bhi), x2, acc2[q]);
            }
        }
#pragma unroll
        for (int q = 0; q < RP; q++) {
            float2 v = unpack2(acc2[q]);
            sAggT[(2 * q) * 32 + lane][w]     = v.x;
            sAggT[(2 * q + 1) * 32 + lane][w] = v.y;
        }
        __syncthreads();

        // ---- GEMM: warp w owns j-slice; W slice loaded per tile (L1-hot,
        //      keeps register liveness disjoint from aggregation) ----
        float Wreg[CJ];
#pragma unroll
        for (int i = 0; i < CJ; i++) Wreg[i] = __ldg(&W[(w * CJ + i) * Cout + coLane]);

        u64 gac[NPAIR];
#pragma unroll
        for (int p = 0; p < NPAIR; p++) gac[p] = 0ull;
#pragma unroll
        for (int i = 0; i < CJ; i++) {
            int j = w * CJ + i;
            u64 w2 = pack2(Wreg[i], Wreg[i]);
#pragma unroll
            for (int p = 0; p < NPAIR; p++) {
                int pp = (Cout == 32) ? p : (p * 2 + hi16);
                u64 a2 = *(const u64*)&sAggT[j][2 * pp];
                gac[p] = fma2(a2, w2, gac[p]);
            }
        }
#pragma unroll
        for (int p = 0; p < NPAIR; p++) {
            int pp = (Cout == 32) ? p : (p * 2 + hi16);
            float2 v = unpack2(gac[p]);
            sPart[(w * 8 + 2 * pp) * Cout + coLane]     = v.x;
            sPart[(w * 8 + 2 * pp + 1) * Cout + coLane] = v.y;
        }
        __syncthreads();

        // ---- reduce partials + epilogue ----
        if (tid < 8 * Cout) {
            int n  = tid / Cout;
            int co = tid % Cout;
            float s = 0.f;
#pragma unroll
            for (int ww = 0; ww < 8; ww++) s += sPart[(ww * 8 + n) * Cout + co];
            int node2 = tile * 8 + n;
            s *= g_invc[node2];
            s = fast_elu(s);
            if (resid) s += resid[(size_t)node2 * Cout + co];
            if (POOL) {
                float px = pos[node2 * 3 + 0], py = pos[node2 * 3 + 1];
                int cx = (int)floorf(px / PSX);
                int cy = (int)floorf(py / PSY);
                int cl = batch[node2] * GCELLS + cy * GXDIM + cx;
                atomicMax(&g_pool[cl * 32 + co], enc_f32(s));
            } else {
                hout[(size_t)node2 * Cout + co] = s;
            }
        }
        __syncthreads();
    }
}

// ---------------- the mega kernel: whole pipeline, one launch ----------------
__global__ void __launch_bounds__(NTHR, 4)
k_mega(const float* __restrict__ x,   const float* __restrict__ pos,
       const float* __restrict__ ea,  const int* __restrict__ ei,
       const int* __restrict__ batch, const float* __restrict__ fcw,
       const float* __restrict__ w1, const float* __restrict__ w2,
       const float* __restrict__ w3, const float* __restrict__ w4,
       const float* __restrict__ w5, const float* __restrict__ w6,
       const float* __restrict__ w7, float* __restrict__ out) {
    __shared__ __align__(16) float sAggT[256][10];
    __shared__ __align__(16) float sPart[2048];
    __shared__ int sScan[256];

    const int tid = threadIdx.x;
    const int gtid = blockIdx.x * NTHR + tid;
    const int* src = ei;
    const int* dst = ei + NEDGES;
    // barrier generation snapshot (read before this block's first arrive)
    unsigned barbase = *(volatile unsigned*)&g_bar_gen;
    __syncthreads();

    // ---- P0: zero counters + pool ----
    for (int i = gtid; i < NNODES; i += NBLK * NTHR) g_cnt[i] = 0;
    for (int i = gtid; i < NBATCH * GCELLS * 32; i += NBLK * NTHR)
        g_pool[i] = 0x007FFFFFu;                      // enc(-inf)
    grid_barrier(barbase + 1);

    // ---- P1: degree count ----
    for (int e = gtid; e < NEDGES; e += NBLK * NTHR)
        atomicAdd(&g_cnt[dst[e]], 1);
    grid_barrier(barbase + 2);

    // ---- P2a: block-local scan (blocks 0..99, 1024 nodes each) ----
    if (blockIdx.x < 100) {
        int b = blockIdx.x;
        int base = b * 1024 + tid * 4;
        int v0 = g_cnt[base + 0], v1 = g_cnt[base + 1];
        int v2 = g_cnt[base + 2], v3 = g_cnt[base + 3];
        int s = v0 + v1 + v2 + v3;
        sScan[tid] = s;
        __syncthreads();
        for (int off = 1; off < 256; off <<= 1) {
            int t = (tid >= off) ? sScan[tid - off] : 0;
            __syncthreads();
            sScan[tid] += t;
            __syncthreads();
        }
        int excl = sScan[tid] - s;
        g_rowp[base + 0] = excl;
        g_rowp[base + 1] = excl + v0;
        g_rowp[base + 2] = excl + v0 + v1;
        g_rowp[base + 3] = excl + v0 + v1 + v2;
        if (tid == 255) g_bsum[b] = sScan[255];
    }
    grid_barrier(barbase + 3);

    // ---- P2b: scan of 100 block sums (block 0) ----
    if (blockIdx.x == 0) {
        int v = (tid < 100) ? g_bsum[tid] : 0;
        sScan[tid] = v;
        __syncthreads();
        for (int off = 1; off < 256; off <<= 1) {
            int a = (tid >= off) ? sScan[tid - off] : 0;
            __syncthreads();
            sScan[tid] += a;
            __syncthreads();
        }
        if (tid < 100) g_bsum[tid] = sScan[tid] - v;
    }
    grid_barrier(barbase + 4);

    // ---- P2c: global row pointers + inverse counts ----
    for (int i = gtid; i < NNODES; i += NBLK * NTHR) {
        int r = g_rowp[i] + g_bsum[i >> 10];
        g_rowp[i] = r;
        g_wcur[i] = r;
        int c = g_cnt[i];
        g_invc[i] = 1.0f / (float)(c > 0 ? c : 1);
    }
    if (gtid == 0) g_rowp[NNODES] = NEDGES;
    grid_barrier(barbase + 5);

    // ---- P3: CSR fill + basis ----
    for (int e = gtid; e < NEDGES; e += NBLK * NTHR) {
        int p = atomicAdd(&g_wcur[dst[e]], 1);
        g_srcs[p] = src[e];
        float u0 = fminf(fmaxf(ea[e * 3 + 0], 0.f), 1.f);
        float u1 = fminf(fmaxf(ea[e * 3 + 1], 0.f), 1.f);
        float u2 = fminf(fmaxf(ea[e * 3 + 2], 0.f), 1.f);
        float m0 = 1.f - u0, m1 = 1.f - u1, m2 = 1.f - u2;
        float4 lo = make_float4(m0 * m1 * m2, u0 * m1 * m2, m0 * u1 * m2, u0 * u1 * m2);
        float4 hi = make_float4(m0 * m1 * u2, u0 * m1 * u2, m0 * u1 * u2, u0 * u1 * u2);
        float4* bo = (float4*)(g_basis + (size_t)p * 8);
        bo[0] = lo; bo[1] = hi;
    }
    grid_barrier(barbase + 6);

    // ---- P4..P10: seven conv layers ----
    conv1_phase(x, g_bufA, w1);
    grid_barrier(barbase + 7);
    conv_phase<8,  16, false>(g_bufA, g_bufB, nullptr, w2, pos, batch, sAggT, sPart);
    grid_barrier(barbase + 8);
    conv_phase<16, 16, false>(g_bufB, g_bufA, nullptr, w3, pos, batch, sAggT, sPart);
    grid_barrier(barbase + 9);
    conv_phase<16, 16, false>(g_bufA, g_bufC, g_bufB, w4, pos, batch, sAggT, sPart);
    grid_barrier(barbase + 10);
    conv_phase<16, 32, false>(g_bufC, g_bufA, nullptr, w5, pos, batch, sAggT, sPart);
    grid_barrier(barbase + 11);
    conv_phase<32, 32, false>(g_bufA, g_bufB, nullptr, w6, pos, batch, sAggT, sPart);
    grid_barrier(barbase + 12);
    conv_phase<32, 32, true >(g_bufB, g_bufC, g_bufA, w7, pos, batch, sAggT, sPart);
    grid_barrier(barbase + 13);

    // ---- P11: FC head (blocks 0..15) ----
    if (blockIdx.x < NBATCH) {
        int b = blockIdx.x;
        float a0 = 0.f, a1 = 0.f;
        for (int j = tid; j < FC_IN; j += NTHR) {
            unsigned u = g_pool[b * FC_IN + j];
            float v = (u & 0x80000000u) ? __uint_as_float(u & 0x7fffffffu)
                                        : __uint_as_float(~u);
            if (!isfinite(v)) v = 0.f;
            a0 = fmaf(v, fcw[j * 2 + 0], a0);
            a1 = fmaf(v, fcw[j * 2 + 1], a1);
        }
        float* s0 = sPart;          // reuse smem
        float* s1 = sPart + 256;
        s0[tid] = a0; s1[tid] = a1;
        __syncthreads();
        for (int o = 128; o > 0; o >>= 1) {
            if (tid < o) { s0[tid] += s0[tid + o]; s1[tid] += s1[tid + o]; }
            __syncthreads();
        }
        if (tid == 0) { out[b * 2 + 0] = s0[0]; out[b * 2 + 1] = s1[0]; }
    }
}

// ---------------- launch ----------------
extern "C" void kernel_launch(void* const* d_in, const int* in_sizes, int n_in,
                              void* d_out, int out_size) {
    const float* x     = (const float*)d_in[0];
    const float* pos   = (const float*)d_in[1];
    const float* ea    = (const float*)d_in[2];
    const int*   ei    = (const int*)  d_in[3];
    const int*   batch = (const int*)  d_in[4];
    const float* fcw   = (const float*)d_in[5];
    const float* w1 = (const float*)d_in[6];
    const float* w2 = (const float*)d_in[7];
    const float* w3 = (const float*)d_in[8];
    const float* w4 = (const float*)d_in[9];
    const float* w5 = (const float*)d_in[10];
    const float* w6 = (const float*)d_in[11];
    const float* w7 = (const float*)d_in[12];

    k_mega<<<NBLK, NTHR>>>(x, pos, ea, ei, batch, fcw,
                           w1, w2, w3, w4, w5, w6, w7, (float*)d_out);
}